// round 17
// baseline (speedup 1.0000x reference)
#include <cuda_runtime.h>
#include <cuda_bf16.h>
#include <math.h>

#define DINLINE __device__ __forceinline__

constexpr int NN = 100000;
constexpr int TT = 24;

// ---------------- scratch globals ----------------
__device__ __align__(16) float g_xw[NN * 32];
__device__ __align__(16) float g_acc[NN * 32];
__device__ __align__(16) float g_gi[NN * 192];          // [n][r(64)|z(64)|in(64)] (+biases)
__device__ __align__(16) __nv_bfloat16 g_B[256 * 152];  // MMA B: n<128: (r,z) pairs; n>=128: (hn,head) pairs
__device__ __align__(16) float g_Wn[64 * 8];            // W_ih n-rows, x cols (fp32, SIMT i_n)
__device__ __align__(16) float g_bhn[64];

DINLINE float sigf(float x)  { return __fdividef(1.0f, 1.0f + __expf(-x)); }
DINLINE float tanh_mufu(float x) { float y; asm("tanh.approx.f32 %0, %1;" : "=f"(y) : "f"(x)); return y; }
DINLINE float sigf_fast(float x) { return fmaf(0.5f, tanh_mufu(0.5f * x), 0.5f); }
DINLINE unsigned s2u(const void* p) {
    unsigned a; asm("{ .reg .u64 t; cvta.to.shared.u64 t, %1; cvt.u32.u64 %0, t; }" : "=r"(a) : "l"(p)); return a;
}
#define LDSM4(r0,r1,r2,r3,addr) \
    asm volatile("ldmatrix.sync.aligned.m8n8.x4.shared.b16 {%0,%1,%2,%3}, [%4];" \
        : "=r"(r0),"=r"(r1),"=r"(r2),"=r"(r3) : "r"(addr))
#define MMA16816(d,a0,a1,a2,a3,b0,b1) \
    asm volatile("mma.sync.aligned.m16n8k16.row.col.f32.bf16.bf16.f32 " \
        "{%0,%1,%2,%3},{%4,%5,%6,%7},{%8,%9},{%0,%1,%2,%3};" \
        : "+f"(d[0]),"+f"(d[1]),"+f"(d[2]),"+f"(d[3]) \
        : "r"(a0),"r"(a1),"r"(a2),"r"(a3),"r"(b0),"r"(b1))

// ---------------- graph conv: 160 nodes / 256-thread block; grid 625 ----------------
__global__ void lin32_kernel(const float* __restrict__ Xext, const float* __restrict__ W,
                             const float* __restrict__ bias, int relu_acc_src) {
    __shared__ float Wt[1024];
    __shared__ float Xs[160 * 33];
    int tid = threadIdx.x, n0 = blockIdx.x * 160;
    for (int e = tid; e < 1024; e += 256) { int j = e >> 5, k = e & 31; Wt[k * 32 + j] = W[j * 32 + k]; }
    for (int e = tid; e < 5120; e += 256) {
        int n = e >> 5, k = e & 31;
        float v = relu_acc_src ? fmaxf(g_acc[(n0 + n) * 32 + k], 0.0f) : Xext[(n0 + n) * 32 + k];
        Xs[n * 33 + k] = v;
    }
    __syncthreads();
    for (int e = tid; e < 5120; e += 256) g_acc[n0 * 32 + e] = 0.0f;
    int j = tid & 31; float b = bias[j];
#pragma unroll 4
    for (int g = 0; g < 20; ++g) {
        int n = (tid >> 5) + g * 8; float acc = b;
#pragma unroll
        for (int k = 0; k < 32; ++k) acc = fmaf(Xs[n * 33 + k], Wt[k * 32 + j], acc);
        g_xw[(n0 + n) * 32 + j] = acc;
    }
}

// ---------------- SpMM: 1 thread / edge, 8 v4-REDs. grid 12500 x 256 ----------------
__global__ void spmm_kernel(const int* __restrict__ er, const int* __restrict__ ec,
                            const float* __restrict__ ev) {
    int e = blockIdx.x * 256 + threadIdx.x;
    int r = __ldg(er + e), c = __ldg(ec + e);
    float v = __ldg(ev + e);
    const float4* src = (const float4*)(g_xw + c * 32);
    float* dst = g_acc + r * 32;
#pragma unroll
    for (int q = 0; q < 8; ++q) {
        float4 x = src[q];
        asm volatile("red.global.add.v4.f32 [%0], {%1, %2, %3, %4};"
                     :: "l"(dst + q * 4), "f"(v * x.x), "f"(v * x.y), "f"(v * x.z), "f"(v * x.w)
                     : "memory");
    }
}

// ---------------- gi_prep: 160 nodes / 256-thread block; grid 625 ----------------
__global__ void gi_prep_kernel(const float* __restrict__ Wih, const float* __restrict__ bih,
                               const float* __restrict__ bhh) {
    __shared__ float Ws[32 * 192];
    __shared__ float Hs[160 * 33];
    int tid = threadIdx.x, n0 = blockIdx.x * 160;
    for (int e = tid; e < 6144; e += 256) { int k = e / 192, j = e - k * 192; Ws[e] = Wih[j * 40 + k]; }
    for (int e = tid; e < 5120; e += 256) {
        int n = e >> 5, k = e & 31;
        Hs[n * 33 + k] = fmaxf(g_acc[(n0 + n) * 32 + k], 0.0f);
    }
    __syncthreads();
#pragma unroll 1
    for (int it = 0; it < 120; ++it) {      // 160*192 = 30720 = 120*256
        int p = it * 256 + tid;
        int n = p / 192, j = p - n * 192;
        float acc = bih[j] + (j < 128 ? bhh[j] : 0.0f);
#pragma unroll
        for (int k = 0; k < 32; ++k) acc = fmaf(Hs[n * 33 + k], Ws[k * 192 + j], acc);
        g_gi[(n0 + n) * 192 + j] = acc;
    }
}

// Pack MMA B matrix (bf16) + Wn + bhn. grid 155 x 256.
__global__ void prep_kernel(const float* __restrict__ Whh, const float* __restrict__ Wih,
                            const float* __restrict__ h1W, const float* __restrict__ bhh) {
    int id = blockIdx.x * 256 + threadIdx.x;
    if (id < 256 * 152) {
        int n = id / 152, k = id - n * 152;
        float w = 0.0f;
        if (n < 128) {
            int j = n >> 1, c = n & 1;            // 0=r, 1=z
            if (k < 64) {
                w = Whh[(c ? 64 + j : j) * 64 + k];
            } else if (k >= 128 && k < 136) {
                w = Wih[(c ? 64 + j : j) * 40 + 32 + (k - 128)];
            }
        } else {
            int n2 = n - 128, j = n2 >> 1, c = n2 & 1;   // 0=hn, 1=head
            if (k < 64) {
                w = c ? h1W[j * 64 + k] : Whh[(128 + j) * 64 + k];
            }
        }
        g_B[id] = __float2bfloat16(w);
    } else if (id < 256 * 152 + 512) {
        int q = id - 256 * 152;
        g_Wn[q] = Wih[(128 + (q >> 3)) * 40 + 32 + (q & 7)];
    } else if (id < 256 * 152 + 512 + 64) {
        g_bhn[id - (256 * 152 + 512)] = bhh[128 + id - (256 * 152 + 512)];
    }
}

// ---------------- persistent tensor-core GRU: single barrier/step (R16, unchanged) ----------------
constexpr int OF_A    = 0;        // 64*168 bf16 = 21504 B = 5376 floats
constexpr int OF_B    = 5376;     // 256*152 bf16 = 77824 B = 19456 floats
constexpr int OF_XF   = 24832;    // [2][64*8] fp32 = 1024
constexpr int OF_WN   = 25856;    // [j][8] fp32 = 512
constexpr int OF_RED  = 26368;    // [2][4][64] = 512
constexpr int OF_BHN  = 26880;
constexpr int OF_H1B  = 26944;
constexpr int OF_H2W  = 27008;
constexpr int OF_H2B  = 27072;
constexpr int GRU_SMEM_FLOATS = 27076;
constexpr int GRU_SMEM_BYTES  = GRU_SMEM_FLOATS * 4;   // 108,304 B
constexpr int SAB_A = 336;
constexpr int SAB_B = 304;

__global__ void __launch_bounds__(512, 1)
gru_mma_kernel(const float* __restrict__ xdyn, const float* __restrict__ h1b,
               const float* __restrict__ h2w, const float* __restrict__ h2b,
               float* __restrict__ yout) {
    extern __shared__ float sm[];
    float*  s_xf   = sm + OF_XF;
    float*  s_wn   = sm + OF_WN;
    float*  s_red  = sm + OF_RED;
    float*  s_bhn  = sm + OF_BHN;
    float*  s_h1b  = sm + OF_H1B;
    float*  s_h2w  = sm + OF_H2W;
    __nv_bfloat16* abf = (__nv_bfloat16*)(sm + OF_A);

    int tid = threadIdx.x;
    int n0  = blockIdx.x * 64;
    int L = tid & 31, wid = tid >> 5;
    int mg = wid >> 2, nh = wid & 3;
    int q = L & 3, rgrp = L >> 2;
    int m0 = mg * 16 + rgrp;

    for (int i = tid; i < 5376; i += 512) sm[OF_A + i] = 0.0f;
    {
        float4* d4 = (float4*)(sm + OF_B);
        const float4* s4 = (const float4*)g_B;
        for (int i = tid; i < 4864; i += 512) d4[i] = s4[i];
    }
    if (tid < 512) s_wn[tid] = g_Wn[tid];
    if (tid < 64) { s_bhn[tid] = g_bhn[tid]; s_h1b[tid] = h1b[tid]; s_h2w[tid] = h2w[tid]; }
    if (tid == 0) sm[OF_H2B] = h2b[0];

    int gm0 = min(n0 + m0, NN - 1);
    int gm1 = min(n0 + m0 + 8, NN - 1);
    float2 grz0[4], grz1[4];
    float  gin0[4], gin1[4];
#pragma unroll
    for (int tp = 0; tp < 4; ++tp) {
        int j = nh * 16 + tp * 4 + q;
        const float* p0 = g_gi + (size_t)gm0 * 192;
        const float* p1 = g_gi + (size_t)gm1 * 192;
        grz0[tp] = make_float2(__ldg(p0 + j), __ldg(p0 + 64 + j));
        grz1[tp] = make_float2(__ldg(p1 + j), __ldg(p1 + 64 + j));
        gin0[tp] = __ldg(p0 + 128 + j);
        gin1[tp] = __ldg(p1 + 128 + j);
    }
    __syncthreads();
    if (tid < 64) {
        int gn = min(n0 + tid, NN - 1);
        const float4* x4 = (const float4*)(xdyn + (size_t)gn * 8);
        float4 a = x4[0], b = x4[1];
        float xv[8] = {a.x, a.y, a.z, a.w, b.x, b.y, b.z, b.w};
        __nv_bfloat16* ax = abf + tid * 168 + 128;
#pragma unroll
        for (int kk = 0; kk < 8; ++kk) { ax[kk] = __float2bfloat16(xv[kk]); s_xf[tid * 8 + kk] = xv[kk]; }
    }
    __syncthreads();

    unsigned smA = s2u(sm);
    unsigned smB = smA + OF_B * 4;
    unsigned aLane  = smA + (unsigned)((mg * 16 + (L & 15)) * SAB_A) + ((L & 16) ? 16u : 0u);
    unsigned bLane1 = smB + (unsigned)((nh * 32 + (L & 7) + ((L & 16) ? 8 : 0)) * SAB_B) + ((L & 8) ? 16u : 0u);
    unsigned bLane2 = bLane1 + (unsigned)(128 * SAB_B);

    float h2b0 = sm[OF_H2B];

    float hreg0[4] = {0.f, 0.f, 0.f, 0.f};
    float hreg1[4] = {0.f, 0.f, 0.f, 0.f};

#pragma unroll 1
    for (int t = 0; t <= TT; ++t) {
        int pw = t & 1;

        if (t >= 2 && tid < 64) {
            const float* rb = s_red + (1 - pw) * 256;
            int gn = n0 + tid;
            if (gn < NN)
                yout[(size_t)(t - 2) * NN + gn] =
                    sigf(rb[tid] + rb[64 + tid] + rb[128 + tid] + rb[192 + tid] + h2b0);
        }
        float4 xpa, xpb;
        if (t < TT - 1 && tid < 64) {
            int gn = min(n0 + tid, NN - 1);
            const float4* x4 = (const float4*)(xdyn + ((size_t)(t + 1) * NN + gn) * 8);
            xpa = x4[0]; xpb = x4[1];
        }

        float acc1[4][4], acc2[4][4];
#pragma unroll
        for (int i = 0; i < 4; ++i) {
            acc1[i][0]=acc1[i][1]=acc1[i][2]=acc1[i][3]=0.0f;
            acc2[i][0]=acc2[i][1]=acc2[i][2]=acc2[i][3]=0.0f;
        }
#pragma unroll
        for (int c = 0; c < 4; ++c) {
            unsigned a0, a1, a2, a3;
            LDSM4(a0, a1, a2, a3, aLane + (pw * 4 + c) * 32);
#pragma unroll
            for (int tb = 0; tb < 2; ++tb) {
                unsigned b0, b1, b2, b3;
                LDSM4(b0, b1, b2, b3, bLane1 + c * 32 + tb * (16 * SAB_B));
                MMA16816(acc1[tb * 2],     a0, a1, a2, a3, b0, b1);
                MMA16816(acc1[tb * 2 + 1], a0, a1, a2, a3, b2, b3);
                LDSM4(b0, b1, b2, b3, bLane2 + c * 32 + tb * (16 * SAB_B));
                MMA16816(acc2[tb * 2],     a0, a1, a2, a3, b0, b1);
                MMA16816(acc2[tb * 2 + 1], a0, a1, a2, a3, b2, b3);
            }
        }
        {
            unsigned a0, a1, a2, a3;
            LDSM4(a0, a1, a2, a3, aLane + (8 + pw) * 32);
#pragma unroll
            for (int tb = 0; tb < 2; ++tb) {
                unsigned b0, b1, b2, b3;
                LDSM4(b0, b1, b2, b3, bLane1 + 8 * 32 + tb * (16 * SAB_B));
                MMA16816(acc1[tb * 2],     a0, a1, a2, a3, b0, b1);
                MMA16816(acc1[tb * 2 + 1], a0, a1, a2, a3, b2, b3);
            }
        }

        float xf0[8], xf1[8];
        {
            const float* xb = s_xf + pw * 512;
#pragma unroll
            for (int k4 = 0; k4 < 2; ++k4) {
                float4 v0 = *(const float4*)(xb + m0 * 8 + k4 * 4);
                float4 v1 = *(const float4*)(xb + (m0 + 8) * 8 + k4 * 4);
                xf0[k4*4+0]=v0.x; xf0[k4*4+1]=v0.y; xf0[k4*4+2]=v0.z; xf0[k4*4+3]=v0.w;
                xf1[k4*4+0]=v1.x; xf1[k4*4+1]=v1.y; xf1[k4*4+2]=v1.z; xf1[k4*4+3]=v1.w;
            }
        }
        int hb = (1 - pw) * 64;
        float hp0 = 0.0f, hp1 = 0.0f;
#pragma unroll
        for (int tp = 0; tp < 4; ++tp) {
            int j = nh * 16 + tp * 4 + q;
            float w2j = s_h2w[j], b1j = s_h1b[j];
            hp0 = fmaf(w2j, fmaxf(acc2[tp][1] + b1j, 0.0f), hp0);
            hp1 = fmaf(w2j, fmaxf(acc2[tp][3] + b1j, 0.0f), hp1);
            if (t < TT) {
                float ain0 = gin0[tp], ain1 = gin1[tp];
                float4 wa = *(const float4*)(s_wn + j * 8);
                float4 wb = *(const float4*)(s_wn + j * 8 + 4);
                ain0 += xf0[0]*wa.x + xf0[1]*wa.y + xf0[2]*wa.z + xf0[3]*wa.w
                      + xf0[4]*wb.x + xf0[5]*wb.y + xf0[6]*wb.z + xf0[7]*wb.w;
                ain1 += xf1[0]*wa.x + xf1[1]*wa.y + xf1[2]*wa.z + xf1[3]*wa.w
                      + xf1[4]*wb.x + xf1[5]*wb.y + xf1[6]*wb.z + xf1[7]*wb.w;
                float bh = s_bhn[j];
                float r0 = sigf_fast(acc1[tp][0] + grz0[tp].x);
                float z0 = sigf_fast(acc1[tp][1] + grz0[tp].y);
                float nn0 = tanh_mufu(ain0 + r0 * (acc2[tp][0] + bh));
                float r1 = sigf_fast(acc1[tp][2] + grz1[tp].x);
                float z1 = sigf_fast(acc1[tp][3] + grz1[tp].y);
                float nn1 = tanh_mufu(ain1 + r1 * (acc2[tp][2] + bh));
                hreg0[tp] = nn0 + z0 * (hreg0[tp] - nn0);
                hreg1[tp] = nn1 + z1 * (hreg1[tp] - nn1);
                abf[m0 * 168 + hb + j]       = __float2bfloat16(hreg0[tp]);
                abf[(m0 + 8) * 168 + hb + j] = __float2bfloat16(hreg1[tp]);
            }
        }
        hp0 += __shfl_xor_sync(0xffffffffu, hp0, 1);
        hp0 += __shfl_xor_sync(0xffffffffu, hp0, 2);
        hp1 += __shfl_xor_sync(0xffffffffu, hp1, 1);
        hp1 += __shfl_xor_sync(0xffffffffu, hp1, 2);
        if (q == 0) { s_red[pw * 256 + nh * 64 + m0] = hp0; s_red[pw * 256 + nh * 64 + m0 + 8] = hp1; }

        if (t < TT - 1 && tid < 64) {
            float xv[8] = {xpa.x, xpa.y, xpa.z, xpa.w, xpb.x, xpb.y, xpb.z, xpb.w};
            __nv_bfloat16* ax = abf + tid * 168 + 128 + (1 - pw) * 16;
            float* xn = s_xf + (1 - pw) * 512 + tid * 8;
#pragma unroll
            for (int kk = 0; kk < 8; ++kk) { ax[kk] = __float2bfloat16(xv[kk]); xn[kk] = xv[kk]; }
        }
        __syncthreads();
    }

    if (tid < 64) {
        const float* rb = s_red + (TT & 1) * 256;
        int gn = n0 + tid;
        if (gn < NN)
            yout[(size_t)(TT - 1) * NN + gn] =
                sigf(rb[tid] + rb[64 + tid] + rb[128 + tid] + rb[192 + tid] + h2b0);
    }
}

// ---------------- launch ----------------
extern "C" void kernel_launch(void* const* d_in, const int* in_sizes, int n_in,
                              void* d_out, int out_size) {
    const float* X_static = (const float*)d_in[0];
    const float* X_dyn    = (const float*)d_in[1];
    const int*   er       = (const int*)d_in[2];
    const int*   ec       = (const int*)d_in[3];
    const float* ev       = (const float*)d_in[4];
    const float* g1W      = (const float*)d_in[5];
    const float* g1b      = (const float*)d_in[6];
    const float* g2W      = (const float*)d_in[7];
    const float* g2b      = (const float*)d_in[8];
    const float* Wih      = (const float*)d_in[9];
    const float* Whh      = (const float*)d_in[10];
    const float* bih      = (const float*)d_in[11];
    const float* bhh      = (const float*)d_in[12];
    const float* h1W      = (const float*)d_in[13];
    const float* h1b      = (const float*)d_in[14];
    const float* h2W      = (const float*)d_in[15];
    const float* h2b      = (const float*)d_in[16];
    float* out = (float*)d_out;

    cudaFuncSetAttribute(gru_mma_kernel,
                         cudaFuncAttributeMaxDynamicSharedMemorySize, GRU_SMEM_BYTES);

    lin32_kernel<<<625, 256>>>(X_static, g1W, g1b, 0);
    spmm_kernel<<<12500, 256>>>(er, ec, ev);
    lin32_kernel<<<625, 256>>>(X_static, g2W, g2b, 1);
    spmm_kernel<<<12500, 256>>>(er, ec, ev);

    prep_kernel<<<155, 256>>>(Whh, Wih, h1W, bhh);
    gi_prep_kernel<<<625, 256>>>(Wih, bih, bhh);

    gru_mma_kernel<<<1563, 512, GRU_SMEM_BYTES>>>(X_dyn, h1b, h2W, h2b, out);
}